// round 1
// baseline (speedup 1.0000x reference)
#include <cuda_runtime.h>

#define NTOK 65536
#define DIM  64
#define KC   4096

// output layout: quantized_st [N*D], loss, perplexity, new_e [D*K], new_cs [K], new_un [D*K]
#define OFF_LOSS 4194304
#define OFF_PERP 4194305
#define OFF_NE   4194306
#define OFF_NCS  4456450
#define OFF_NUN  4460546

typedef unsigned long long ull;

// ---------------- device scratch (no allocations allowed) ----------------
__device__ float g_eT[KC * DIM];        // embeddings transposed [K, D] for coalesced gather
__device__ float g_ee[KC];              // ||e_k||^2
__device__ int   g_idx[NTOK];           // argmin indices
__device__ float g_counts[KC];
__device__ float g_sums[KC * DIM];      // per-cluster sum of x, [K, D]
__device__ float g_losspart[NTOK / 4];  // per-block loss partials
__device__ float g_scal[2];             // [0]=n_sum, [1]=entropy_sum

// ---------------- f32x2 helpers ----------------
__device__ __forceinline__ ull dup2(float v) {
    ull r;
    asm("mov.b64 %0, {%1, %1};" : "=l"(r) : "f"(v));
    return r;
}
__device__ __forceinline__ ull pack2(float lo, float hi) {
    ull r;
    asm("mov.b64 %0, {%1, %2};" : "=l"(r) : "f"(lo), "f"(hi));
    return r;
}
__device__ __forceinline__ void fma2(ull &acc, ull a, ull b) {
    asm("fma.rn.f32x2 %0, %1, %2, %0;" : "+l"(acc) : "l"(a), "l"(b));
}
__device__ __forceinline__ float2 unpack2(ull v) {
    float lo, hi;
    asm("mov.b64 {%0, %1}, %2;" : "=f"(lo), "=f"(hi) : "l"(v));
    return make_float2(lo, hi);
}

// ---------------- kernel 1: zero scratch ----------------
__global__ void zero_kernel() {
    int i = blockIdx.x * blockDim.x + threadIdx.x;   // 262144 threads
    if (i < KC) g_counts[i] = 0.f;
    if (i < 2)  g_scal[i]   = 0.f;
    if (i < KC * DIM) g_sums[i] = 0.f;
}

// ---------------- kernel 2: ||e_k||^2 and transpose ----------------
__global__ void prep_kernel(const float* __restrict__ e) {
    int k = blockIdx.x * blockDim.x + threadIdx.x;
    float s = 0.f;
    #pragma unroll
    for (int d = 0; d < DIM; d++) {
        float v = e[d * KC + k];
        g_eT[k * DIM + d] = v;
        s = fmaf(v, v, s);
    }
    g_ee[k] = s;
}

// ---------------- kernel 3: fused distance GEMM + argmin ----------------
// CTA tile: 64 tokens x 128 codes, loop over all K. 256 threads,
// micro-tile 4 tokens x 8 codes, f32x2-packed accumulation.
#define BM 64
#define BN 128

__global__ __launch_bounds__(256) void argmin_kernel(const float* __restrict__ x,
                                                     const float* __restrict__ e) {
    __shared__ float As[DIM][BM];   // 16 KB, d-major (transposed x tile)
    __shared__ float Bs[DIM][BN];   // 32 KB
    const int tid = threadIdx.x;
    const int m0  = blockIdx.x * BM;
    const int tx  = tid & 15;       // 16 code groups
    const int ty  = tid >> 4;       // 16 token groups (4 tokens each)

    // load A tile transposed (one-time)
    #pragma unroll
    for (int i = 0; i < 4; i++) {
        int lin = tid + i * 256;            // float4 index, 1024 total
        int r = lin >> 4;
        int c = (lin & 15) << 2;
        float4 v = *reinterpret_cast<const float4*>(&x[(m0 + r) * DIM + c]);
        As[c + 0][r] = v.x; As[c + 1][r] = v.y; As[c + 2][r] = v.z; As[c + 3][r] = v.w;
    }

    float best[4] = {3.0e38f, 3.0e38f, 3.0e38f, 3.0e38f};
    int   bidx[4] = {0, 0, 0, 0};

    for (int k0 = 0; k0 < KC; k0 += BN) {
        __syncthreads();
        #pragma unroll
        for (int i = 0; i < 8; i++) {
            int lin = tid + i * 256;        // 2048 float4
            int d = lin >> 5;
            int c = (lin & 31) << 2;
            *reinterpret_cast<float4*>(&Bs[d][c]) =
                *reinterpret_cast<const float4*>(&e[d * KC + k0 + c]);
        }
        __syncthreads();

        // acc[i][p]: token i, code pair p. pairs 0,1 -> codes tx*4+{0..3};
        // pairs 2,3 -> codes 64+tx*4+{0..3} (split halves keep LDS conflict-free)
        ull acc[4][4];
        #pragma unroll
        for (int i = 0; i < 4; i++)
            #pragma unroll
            for (int p = 0; p < 4; p++) acc[i][p] = 0ULL;

        #pragma unroll 16
        for (int d = 0; d < DIM; d++) {
            float4 av = *reinterpret_cast<const float4*>(&As[d][ty * 4]);
            ull a[4];
            a[0] = dup2(av.x); a[1] = dup2(av.y); a[2] = dup2(av.z); a[3] = dup2(av.w);
            float4 b0 = *reinterpret_cast<const float4*>(&Bs[d][tx * 4]);
            float4 b1 = *reinterpret_cast<const float4*>(&Bs[d][64 + tx * 4]);
            ull bp[4];
            bp[0] = pack2(b0.x, b0.y);
            bp[1] = pack2(b0.z, b0.w);
            bp[2] = pack2(b1.x, b1.y);
            bp[3] = pack2(b1.z, b1.w);
            #pragma unroll
            for (int i = 0; i < 4; i++)
                #pragma unroll
                for (int p = 0; p < 4; p++)
                    fma2(acc[i][p], a[i], bp[p]);
        }

        // epilogue: score = ||e||^2 - 2 x.e ; running argmin (ascending k, strict <)
        #pragma unroll
        for (int p = 0; p < 4; p++) {
            int kbase = k0 + ((p < 2) ? (tx * 4 + p * 2) : (64 + tx * 4 + (p - 2) * 2));
            float ee0 = g_ee[kbase];
            float ee1 = g_ee[kbase + 1];
            #pragma unroll
            for (int i = 0; i < 4; i++) {
                float2 s = unpack2(acc[i][p]);
                float s0 = fmaf(-2.f, s.x, ee0);
                float s1 = fmaf(-2.f, s.y, ee1);
                if (s0 < best[i]) { best[i] = s0; bidx[i] = kbase; }
                if (s1 < best[i]) { best[i] = s1; bidx[i] = kbase + 1; }
            }
        }
    }

    // reduce across the 16 tx threads of each token group (half-warp segments)
    #pragma unroll
    for (int i = 0; i < 4; i++) {
        float v = best[i];
        int   id = bidx[i];
        #pragma unroll
        for (int off = 8; off > 0; off >>= 1) {
            float v2 = __shfl_down_sync(0xffffffffu, v, off, 16);
            int  id2 = __shfl_down_sync(0xffffffffu, id, off, 16);
            if (v2 < v || (v2 == v && id2 < id)) { v = v2; id = id2; }
        }
        if (tx == 0) g_idx[m0 + ty * 4 + i] = id;
    }
}

// ---------------- kernel 4: gather/quantize + loss + EMA scatter ----------------
__global__ __launch_bounds__(256) void quant_kernel(const float* __restrict__ x,
                                                    float* __restrict__ out) {
    int t   = threadIdx.x;
    int tok = blockIdx.x * 4 + (t >> 6);
    int d   = t & 63;
    int idx = g_idx[tok];
    float xv = x[tok * DIM + d];
    float q  = g_eT[idx * DIM + d];
    out[tok * DIM + d] = xv + (q - xv);          // straight-through, ref arithmetic
    float diff = q - xv;
    float l = diff * diff;
    #pragma unroll
    for (int off = 16; off; off >>= 1) l += __shfl_down_sync(0xffffffffu, l, off);
    __shared__ float part[8];
    if ((t & 31) == 0) part[t >> 5] = l;
    if (d == 0) atomicAdd(&g_counts[idx], 1.0f);
    atomicAdd(&g_sums[idx * DIM + d], xv);
    __syncthreads();
    if (t == 0) {
        float s = 0.f;
        #pragma unroll
        for (int w = 0; w < 8; w++) s += part[w];
        g_losspart[blockIdx.x] = s;
    }
}

// ---------------- kernel 5: loss reduction ----------------
__global__ void loss_kernel(float* __restrict__ out) {
    int t = threadIdx.x;
    float s = 0.f;
    for (int i = t; i < NTOK / 4; i += 256) s += g_losspart[i];
    #pragma unroll
    for (int off = 16; off; off >>= 1) s += __shfl_down_sync(0xffffffffu, s, off);
    __shared__ float part[8];
    if ((t & 31) == 0) part[t >> 5] = s;
    __syncthreads();
    if (t == 0) {
        float tt = 0.f;
        #pragma unroll
        for (int w = 0; w < 8; w++) tt += part[w];
        out[OFF_LOSS] = tt * (0.25f / (float)(NTOK * DIM));
    }
}

// ---------------- kernel 6: new_cs + reductions for n and entropy ----------------
__global__ __launch_bounds__(256) void newcs_kernel(const float* __restrict__ cs,
                                                    float* __restrict__ out) {
    int t = threadIdx.x;
    int k = blockIdx.x * 256 + t;
    float cnt = g_counts[k];
    float ncs = 0.1f * cnt + 0.9f * cs[k];
    out[OFF_NCS + k] = ncs;
    float avg = cnt * (1.0f / (float)NTOK);
    float ent = avg * logf(avg + 1e-20f);
    #pragma unroll
    for (int off = 16; off; off >>= 1) {
        ncs += __shfl_down_sync(0xffffffffu, ncs, off);
        ent += __shfl_down_sync(0xffffffffu, ent, off);
    }
    __shared__ float p1[8], p2[8];
    if ((t & 31) == 0) { p1[t >> 5] = ncs; p2[t >> 5] = ent; }
    __syncthreads();
    if (t == 0) {
        float s1 = 0.f, s2 = 0.f;
        #pragma unroll
        for (int w = 0; w < 8; w++) { s1 += p1[w]; s2 += p2[w]; }
        atomicAdd(&g_scal[0], s1);
        atomicAdd(&g_scal[1], s2);
    }
}

// ---------------- kernel 7: new_un, new_e, perplexity ----------------
__global__ __launch_bounds__(256) void final_kernel(const float* __restrict__ cs,
                                                    const float* __restrict__ un,
                                                    float* __restrict__ out) {
    int lin = blockIdx.x * 256 + threadIdx.x;   // 0..262143 over [D, K]
    int d = lin >> 12;
    int k = lin & (KC - 1);
    float nun = 0.1f * g_sums[k * DIM + d] + 0.9f * un[lin];
    out[OFF_NUN + lin] = nun;
    float n   = g_scal[0];
    float ncs = 0.1f * g_counts[k] + 0.9f * cs[k];
    float stable = (ncs + 1e-20f) / (n + 4.096e-17f) * n;
    out[OFF_NE + lin] = nun / stable;
    if (lin == 0) out[OFF_PERP] = expf(-g_scal[1]);
}

// ---------------- launch ----------------
extern "C" void kernel_launch(void* const* d_in, const int* in_sizes, int n_in,
                              void* d_out, int out_size) {
    const float* x  = (const float*)d_in[0];   // [N, D]
    const float* e  = (const float*)d_in[1];   // [D, K]
    const float* cs = (const float*)d_in[2];   // [K]
    const float* un = (const float*)d_in[3];   // [D, K]
    float* out = (float*)d_out;

    zero_kernel<<<1024, 256>>>();
    prep_kernel<<<KC / 256, 256>>>(e);
    argmin_kernel<<<NTOK / BM, 256>>>(x, e);
    quant_kernel<<<NTOK / 4, 256>>>(x, out);
    loss_kernel<<<1, 256>>>(out);
    newcs_kernel<<<KC / 256, 256>>>(cs, out);
    final_kernel<<<DIM * KC / 256, 256>>>(cs, un, out);
}

// round 2
// speedup vs baseline: 1.0113x; 1.0113x over previous
#include <cuda_runtime.h>

#define NTOK 65536
#define DIM  64
#define KC   4096
#define KSPLIT 4
#define KPER (KC / KSPLIT)   // 1024

// output layout: quantized_st [N*D], loss, perplexity, new_e [D*K], new_cs [K], new_un [D*K]
#define OFF_LOSS 4194304
#define OFF_PERP 4194305
#define OFF_NE   4194306
#define OFF_NCS  4456450
#define OFF_NUN  4460546

typedef unsigned long long ull;

// ---------------- device scratch (no allocations allowed) ----------------
__device__ float g_eT[KC * DIM];        // embeddings transposed [K, D] for coalesced gather
__device__ float g_ee[KC];              // ||e_k||^2
__device__ int   g_idx[NTOK];           // final argmin indices
__device__ float g_pval[NTOK * KSPLIT]; // per-split best value
__device__ int   g_pidx[NTOK * KSPLIT]; // per-split best index
__device__ float g_counts[KC];
__device__ float g_sums[KC * DIM];      // per-cluster sum of x, [K, D]
__device__ float g_losspart[NTOK / 4];  // per-block loss partials
__device__ float g_scal[2];             // [0]=n_sum, [1]=entropy_sum

// ---------------- f32x2 helpers ----------------
__device__ __forceinline__ ull dup2(float v) {
    ull r;
    asm("mov.b64 %0, {%1, %1};" : "=l"(r) : "f"(v));
    return r;
}
__device__ __forceinline__ ull pack2(float lo, float hi) {
    ull r;
    asm("mov.b64 %0, {%1, %2};" : "=l"(r) : "f"(lo), "f"(hi));
    return r;
}
__device__ __forceinline__ void fma2(ull &acc, ull a, ull b) {
    asm("fma.rn.f32x2 %0, %1, %2, %0;" : "+l"(acc) : "l"(a), "l"(b));
}
__device__ __forceinline__ float2 unpack2(ull v) {
    float lo, hi;
    asm("mov.b64 {%0, %1}, %2;" : "=f"(lo), "=f"(hi) : "l"(v));
    return make_float2(lo, hi);
}

// ---------------- kernel 1: prep (||e||^2, transpose) + zero scratch ----------------
__global__ void prep_kernel(const float* __restrict__ e) {
    int k = blockIdx.x * blockDim.x + threadIdx.x;
    float s = 0.f;
    #pragma unroll
    for (int d = 0; d < DIM; d++) {
        float v = e[d * KC + k];
        g_eT[k * DIM + d] = v;
        g_sums[k * DIM + d] = 0.f;
        s = fmaf(v, v, s);
    }
    g_ee[k] = s;
    g_counts[k] = 0.f;
    if (k < 2) g_scal[k] = 0.f;
}

// ---------------- kernel 2: fused distance GEMM + partial argmin (split-K) ----------
// CTA tile: 64 tokens x 1024 codes (one K-split). 256 threads,
// micro-tile 4 tokens x 8 codes, f32x2-packed accumulation.
#define BM 64
#define BN 128

__global__ __launch_bounds__(256, 3) void argmin_kernel(const float* __restrict__ x,
                                                        const float* __restrict__ e) {
    __shared__ float As[DIM][BM];   // 16 KB, d-major (transposed x tile)
    __shared__ float Bs[DIM][BN];   // 32 KB
    const int tid  = threadIdx.x;
    const int m0   = blockIdx.x * BM;
    const int kbeg = blockIdx.y * KPER;
    const int tx   = tid & 15;       // 16 code groups
    const int ty   = tid >> 4;       // 16 token groups (4 tokens each)

    // load A tile transposed (one-time)
    #pragma unroll
    for (int i = 0; i < 4; i++) {
        int lin = tid + i * 256;            // float4 index, 1024 total
        int r = lin >> 4;
        int c = (lin & 15) << 2;
        float4 v = *reinterpret_cast<const float4*>(&x[(m0 + r) * DIM + c]);
        As[c + 0][r] = v.x; As[c + 1][r] = v.y; As[c + 2][r] = v.z; As[c + 3][r] = v.w;
    }

    float best[4] = {3.0e38f, 3.0e38f, 3.0e38f, 3.0e38f};
    int   bidx[4] = {0, 0, 0, 0};

    for (int k0 = kbeg; k0 < kbeg + KPER; k0 += BN) {
        __syncthreads();
        #pragma unroll
        for (int i = 0; i < 8; i++) {
            int lin = tid + i * 256;        // 2048 float4
            int d = lin >> 5;
            int c = (lin & 31) << 2;
            *reinterpret_cast<float4*>(&Bs[d][c]) =
                *reinterpret_cast<const float4*>(&e[d * KC + k0 + c]);
        }
        __syncthreads();

        // acc[i][p]: token i, code pair p. pairs 0,1 -> codes tx*4+{0..3};
        // pairs 2,3 -> codes 64+tx*4+{0..3} (split halves keep LDS conflict-free)
        ull acc[4][4];
        #pragma unroll
        for (int i = 0; i < 4; i++)
            #pragma unroll
            for (int p = 0; p < 4; p++) acc[i][p] = 0ULL;

        #pragma unroll 16
        for (int d = 0; d < DIM; d++) {
            float4 av = *reinterpret_cast<const float4*>(&As[d][ty * 4]);
            ull a[4];
            a[0] = dup2(av.x); a[1] = dup2(av.y); a[2] = dup2(av.z); a[3] = dup2(av.w);
            float4 b0 = *reinterpret_cast<const float4*>(&Bs[d][tx * 4]);
            float4 b1 = *reinterpret_cast<const float4*>(&Bs[d][64 + tx * 4]);
            ull bp[4];
            bp[0] = pack2(b0.x, b0.y);
            bp[1] = pack2(b0.z, b0.w);
            bp[2] = pack2(b1.x, b1.y);
            bp[3] = pack2(b1.z, b1.w);
            #pragma unroll
            for (int i = 0; i < 4; i++)
                #pragma unroll
                for (int p = 0; p < 4; p++)
                    fma2(acc[i][p], a[i], bp[p]);
        }

        // epilogue: score = ||e||^2 - 2 x.e ; running argmin (ascending k, strict <)
        #pragma unroll
        for (int p = 0; p < 4; p++) {
            int kbase = k0 + ((p < 2) ? (tx * 4 + p * 2) : (64 + tx * 4 + (p - 2) * 2));
            float ee0 = g_ee[kbase];
            float ee1 = g_ee[kbase + 1];
            #pragma unroll
            for (int i = 0; i < 4; i++) {
                float2 s = unpack2(acc[i][p]);
                float s0 = fmaf(-2.f, s.x, ee0);
                float s1 = fmaf(-2.f, s.y, ee1);
                if (s0 < best[i]) { best[i] = s0; bidx[i] = kbase; }
                if (s1 < best[i]) { best[i] = s1; bidx[i] = kbase + 1; }
            }
        }
    }

    // reduce across the 16 tx threads of each token group (half-warp segments)
    #pragma unroll
    for (int i = 0; i < 4; i++) {
        float v = best[i];
        int   id = bidx[i];
        #pragma unroll
        for (int off = 8; off > 0; off >>= 1) {
            float v2 = __shfl_down_sync(0xffffffffu, v, off, 16);
            int  id2 = __shfl_down_sync(0xffffffffu, id, off, 16);
            if (v2 < v || (v2 == v && id2 < id)) { v = v2; id = id2; }
        }
        if (tx == 0) {
            int tok = m0 + ty * 4 + i;
            g_pval[tok * KSPLIT + blockIdx.y] = v;
            g_pidx[tok * KSPLIT + blockIdx.y] = id;
        }
    }
}

// ---------------- kernel 3: combine split-K partials ----------------
__global__ void combine_kernel() {
    int tok = blockIdx.x * blockDim.x + threadIdx.x;
    float v = g_pval[tok * KSPLIT];
    int  id = g_pidx[tok * KSPLIT];
    #pragma unroll
    for (int s = 1; s < KSPLIT; s++) {
        float v2 = g_pval[tok * KSPLIT + s];
        int  id2 = g_pidx[tok * KSPLIT + s];
        if (v2 < v) { v = v2; id = id2; }   // ascending split order => first-min tiebreak
    }
    g_idx[tok] = id;
}

// ---------------- kernel 4: gather/quantize + loss + EMA scatter ----------------
__global__ __launch_bounds__(256) void quant_kernel(const float* __restrict__ x,
                                                    float* __restrict__ out) {
    int t   = threadIdx.x;
    int tok = blockIdx.x * 4 + (t >> 6);
    int d   = t & 63;
    int idx = g_idx[tok];
    float xv = x[tok * DIM + d];
    float q  = g_eT[idx * DIM + d];
    out[tok * DIM + d] = xv + (q - xv);          // straight-through, ref arithmetic
    float diff = q - xv;
    float l = diff * diff;
    #pragma unroll
    for (int off = 16; off; off >>= 1) l += __shfl_down_sync(0xffffffffu, l, off);
    __shared__ float part[8];
    if ((t & 31) == 0) part[t >> 5] = l;
    if (d == 0) atomicAdd(&g_counts[idx], 1.0f);
    atomicAdd(&g_sums[idx * DIM + d], xv);
    __syncthreads();
    if (t == 0) {
        float s = 0.f;
        #pragma unroll
        for (int w = 0; w < 8; w++) s += part[w];
        g_losspart[blockIdx.x] = s;
    }
}

// ---------------- kernel 5: loss reduction ----------------
__global__ void loss_kernel(float* __restrict__ out) {
    int t = threadIdx.x;
    float s = 0.f;
    for (int i = t; i < NTOK / 4; i += 256) s += g_losspart[i];
    #pragma unroll
    for (int off = 16; off; off >>= 1) s += __shfl_down_sync(0xffffffffu, s, off);
    __shared__ float part[8];
    if ((t & 31) == 0) part[t >> 5] = s;
    __syncthreads();
    if (t == 0) {
        float tt = 0.f;
        #pragma unroll
        for (int w = 0; w < 8; w++) tt += part[w];
        out[OFF_LOSS] = tt * (0.25f / (float)(NTOK * DIM));
    }
}

// ---------------- kernel 6: new_cs + reductions for n and entropy ----------------
__global__ __launch_bounds__(256) void newcs_kernel(const float* __restrict__ cs,
                                                    float* __restrict__ out) {
    int t = threadIdx.x;
    int k = blockIdx.x * 256 + t;
    float cnt = g_counts[k];
    float ncs = 0.1f * cnt + 0.9f * cs[k];
    out[OFF_NCS + k] = ncs;
    float avg = cnt * (1.0f / (float)NTOK);
    float ent = avg * logf(avg + 1e-20f);
    #pragma unroll
    for (int off = 16; off; off >>= 1) {
        ncs += __shfl_down_sync(0xffffffffu, ncs, off);
        ent += __shfl_down_sync(0xffffffffu, ent, off);
    }
    __shared__ float p1[8], p2[8];
    if ((t & 31) == 0) { p1[t >> 5] = ncs; p2[t >> 5] = ent; }
    __syncthreads();
    if (t == 0) {
        float s1 = 0.f, s2 = 0.f;
        #pragma unroll
        for (int w = 0; w < 8; w++) { s1 += p1[w]; s2 += p2[w]; }
        atomicAdd(&g_scal[0], s1);
        atomicAdd(&g_scal[1], s2);
    }
}

// ---------------- kernel 7: new_un, new_e, perplexity ----------------
__global__ __launch_bounds__(256) void final_kernel(const float* __restrict__ cs,
                                                    const float* __restrict__ un,
                                                    float* __restrict__ out) {
    int lin = blockIdx.x * 256 + threadIdx.x;   // 0..262143 over [D, K]
    int d = lin >> 12;
    int k = lin & (KC - 1);
    float nun = 0.1f * g_sums[k * DIM + d] + 0.9f * un[lin];
    out[OFF_NUN + lin] = nun;
    float n   = g_scal[0];
    float ncs = 0.1f * g_counts[k] + 0.9f * cs[k];
    float stable = (ncs + 1e-20f) / (n + 4.096e-17f) * n;
    out[OFF_NE + lin] = nun / stable;
    if (lin == 0) out[OFF_PERP] = expf(-g_scal[1]);
}

// ---------------- launch ----------------
extern "C" void kernel_launch(void* const* d_in, const int* in_sizes, int n_in,
                              void* d_out, int out_size) {
    const float* x  = (const float*)d_in[0];   // [N, D]
    const float* e  = (const float*)d_in[1];   // [D, K]
    const float* cs = (const float*)d_in[2];   // [K]
    const float* un = (const float*)d_in[3];   // [D, K]
    float* out = (float*)d_out;

    prep_kernel<<<KC / 256, 256>>>(e);
    dim3 agrid(NTOK / BM, KSPLIT);
    argmin_kernel<<<agrid, 256>>>(x, e);
    combine_kernel<<<NTOK / 256, 256>>>();
    quant_kernel<<<NTOK / 4, 256>>>(x, out);
    loss_kernel<<<1, 256>>>(out);
    newcs_kernel<<<KC / 256, 256>>>(cs, out);
    final_kernel<<<DIM * KC / 256, 256>>>(cs, un, out);
}